// round 4
// baseline (speedup 1.0000x reference)
#include <cuda_runtime.h>

// ---------------------------------------------------------------------------
// PhongCircleRenderer — R4
//
// out[pixel] = (idx[pixel,0] < 0) ? (1,1,1) : shaded[idx[pixel,0]]
//
// R4 vs R3 (33.5us):
//  - shade kept as R3 (ILP2 + ldcs: 14 -> 10.8us)
//  - composite: ILP=4 via split-quarters, 4 INDEPENDENT idx->gather->store
//    chains per thread (no cross-chain packing, unlike R2). Goal: interleave
//    L1tex wavefronts from different LDG instructions (1.0 cyc/wf cross-LDG
//    vs 2.07 within-LDG replay rate).
// ---------------------------------------------------------------------------

#define P_MAX 1200000

__device__ float4 g_shaded[P_MAX];   // shaded RGB per point (w-padded)

__device__ __forceinline__ float4 shade_one(
    float px, float py, float pz,
    float nx, float ny, float nz,
    float fr, float fg, float fb,
    float cx, float cy, float cz,
    float lx, float ly, float lz)
{
    float ndl     = nx * lx + ny * ly + nz * lz;
    float diffuse = fmaxf(ndl, 0.0f);

    float vx = cx - px, vy = cy - py, vz = cz - pz;
    {
        float n  = sqrtf(vx * vx + vy * vy + vz * vz);
        float vi = 1.0f / fmaxf(n, 1e-12f);
        vx *= vi; vy *= vi; vz *= vi;
    }
    float hx = lx + vx, hy = ly + vy, hz = lz + vz;
    {
        float n  = sqrtf(hx * hx + hy * hy + hz * hz);
        float hi = 1.0f / fmaxf(n, 1e-12f);
        hx *= hi; hy *= hi; hz *= hi;
    }
    float ndh = fmaxf(nx * hx + ny * hy + nz * hz, 0.0f);
    float x2  = ndh * ndh;
    float x4  = x2 * x2;
    float x8  = x4 * x4;
    float x16 = x8 * x8;
    float spec = x16 * x16;                 // ndh^32 exact (5 squarings)

    float scale = 0.3f + 0.7f * diffuse;
    float sterm = 0.2f * spec;

    float r = fminf(fmaxf(fr * scale + sterm, 0.0f), 1.0f);
    float g = fminf(fmaxf(fg * scale + sterm, 0.0f), 1.0f);
    float b = fminf(fmaxf(fb * scale + sterm, 0.0f), 1.0f);
    return make_float4(r, g, b, 0.0f);
}

__global__ void __launch_bounds__(256)
shade_kernel(const float* __restrict__ points,
             const float* __restrict__ features,
             const float* __restrict__ normals,
             const float* __restrict__ cam_centers,
             const float* __restrict__ light_dir,
             int P, int half, int pts_per_cloud)
{
    int t = blockIdx.x * blockDim.x + threadIdx.x;
    if (t >= half) return;

    int pA = t;
    int pB = t + half;
    bool hasB = (pB < P);

    float lx = __ldg(&light_dir[0]);
    float ly = __ldg(&light_dir[1]);
    float lz = __ldg(&light_dir[2]);
    {
        float n  = sqrtf(lx * lx + ly * ly + lz * lz);
        float li = 1.0f / fmaxf(n, 1e-12f);
        lx *= li; ly *= li; lz *= li;
    }

    float pxA = __ldcs(&points[3 * pA + 0]);
    float pyA = __ldcs(&points[3 * pA + 1]);
    float pzA = __ldcs(&points[3 * pA + 2]);
    float nxA = __ldcs(&normals[3 * pA + 0]);
    float nyA = __ldcs(&normals[3 * pA + 1]);
    float nzA = __ldcs(&normals[3 * pA + 2]);
    float frA = __ldcs(&features[3 * pA + 0]);
    float fgA = __ldcs(&features[3 * pA + 1]);
    float fbA = __ldcs(&features[3 * pA + 2]);

    int pBs = hasB ? pB : pA;
    float pxB = __ldcs(&points[3 * pBs + 0]);
    float pyB = __ldcs(&points[3 * pBs + 1]);
    float pzB = __ldcs(&points[3 * pBs + 2]);
    float nxB = __ldcs(&normals[3 * pBs + 0]);
    float nyB = __ldcs(&normals[3 * pBs + 1]);
    float nzB = __ldcs(&normals[3 * pBs + 2]);
    float frB = __ldcs(&features[3 * pBs + 0]);
    float fgB = __ldcs(&features[3 * pBs + 1]);
    float fbB = __ldcs(&features[3 * pBs + 2]);

    int cA = pA / pts_per_cloud;
    int cB = pBs / pts_per_cloud;
    float cxA = __ldg(&cam_centers[3 * cA + 0]);
    float cyA = __ldg(&cam_centers[3 * cA + 1]);
    float czA = __ldg(&cam_centers[3 * cA + 2]);
    float cxB = __ldg(&cam_centers[3 * cB + 0]);
    float cyB = __ldg(&cam_centers[3 * cB + 1]);
    float czB = __ldg(&cam_centers[3 * cB + 2]);

    g_shaded[pA] = shade_one(pxA, pyA, pzA, nxA, nyA, nzA, frA, fgA, fbA,
                             cxA, cyA, czA, lx, ly, lz);
    if (hasB) {
        g_shaded[pB] = shade_one(pxB, pyB, pzB, nxB, nyB, nzB, frB, fgB, fbB,
                                 cxB, cyB, czB, lx, ly, lz);
    }
}

__global__ void __launch_bounds__(256)
composite_kernel(const int* __restrict__ idx,
                 float*     __restrict__ out,
                 int npix, int quarter, int K)
{
    int t = blockIdx.x * blockDim.x + threadIdx.x;
    if (t >= quarter) return;

    // 4 independent chains at split-quarter offsets: identical coalescing
    // per chain as the 1-pixel/thread version, 4x instruction-level overlap.
    int i0 = t;
    int i1 = t +     quarter;
    int i2 = t + 2 * quarter;
    int i3 = t + 3 * quarter;
    bool h1 = (i1 < npix), h2 = (i2 < npix), h3 = (i3 < npix);
    int s1 = h1 ? i1 : i0;
    int s2 = h2 ? i2 : i0;
    int s3 = h3 ? i3 : i0;

    // front-batched independent idx loads
    int id0 = __ldcs(&idx[(long long)i0 * K]);
    int id1 = __ldcs(&idx[(long long)s1 * K]);
    int id2 = __ldcs(&idx[(long long)s2 * K]);
    int id3 = __ldcs(&idx[(long long)s3 * K]);

    // independent gathers (each arms as soon as its own idx lands)
    float4 v0 = (id0 >= 0) ? g_shaded[id0] : make_float4(1.f, 1.f, 1.f, 0.f);
    float4 v1 = (id1 >= 0) ? g_shaded[id1] : make_float4(1.f, 1.f, 1.f, 0.f);
    float4 v2 = (id2 >= 0) ? g_shaded[id2] : make_float4(1.f, 1.f, 1.f, 0.f);
    float4 v3 = (id3 >= 0) ? g_shaded[id3] : make_float4(1.f, 1.f, 1.f, 0.f);

    // per-chain stores, no cross-chain data coupling
    __stcs(&out[3 * i0 + 0], v0.x);
    __stcs(&out[3 * i0 + 1], v0.y);
    __stcs(&out[3 * i0 + 2], v0.z);
    if (h1) {
        __stcs(&out[3 * i1 + 0], v1.x);
        __stcs(&out[3 * i1 + 1], v1.y);
        __stcs(&out[3 * i1 + 2], v1.z);
    }
    if (h2) {
        __stcs(&out[3 * i2 + 0], v2.x);
        __stcs(&out[3 * i2 + 1], v2.y);
        __stcs(&out[3 * i2 + 2], v2.z);
    }
    if (h3) {
        __stcs(&out[3 * i3 + 0], v3.x);
        __stcs(&out[3 * i3 + 1], v3.y);
        __stcs(&out[3 * i3 + 2], v3.z);
    }
}

extern "C" void kernel_launch(void* const* d_in, const int* in_sizes, int n_in,
                              void* d_out, int out_size)
{
    const int*   idx         = (const int*)  d_in[0];
    const float* points      = (const float*)d_in[1];
    const float* features    = (const float*)d_in[2];
    const float* normals     = (const float*)d_in[3];
    const float* cam_centers = (const float*)d_in[4];
    const float* light_dir   = (const float*)d_in[6];
    float*       out         = (float*)d_out;

    int P = in_sizes[5];
    if (P > P_MAX) P = P_MAX;
    int B    = in_sizes[4] / 3;
    int ppc  = P / B;
    int npix = out_size / 3;
    int K    = in_sizes[0] / npix;

    {
        int half    = (P + 1) / 2;
        int threads = 256;
        int blocks  = (half + threads - 1) / threads;
        shade_kernel<<<blocks, threads>>>(points, features, normals,
                                          cam_centers, light_dir, P, half, ppc);
    }
    {
        int quarter = (npix + 3) / 4;
        int threads = 256;
        int blocks  = (quarter + threads - 1) / threads;
        composite_kernel<<<blocks, threads>>>(idx, out, npix, quarter, K);
    }
}

// round 5
// speedup vs baseline: 1.1783x; 1.1783x over previous
#include <cuda_runtime.h>

// ---------------------------------------------------------------------------
// PhongCircleRenderer — R5
//
// out[pixel] = (idx[pixel,0] < 0) ? (1,1,1) : shaded[idx[pixel,0]]
//
// R5 vs R3 (33.5us best):
//  - shade unchanged (R3 ILP2 + ldcs, ~10.8us, at its DRAM roofline)
//  - composite: persistent SINGLE-WAVE grid-stride kernel
//      * grid = SMs * 8 blocks (exactly one resident wave -> no wave
//        quantization, which post-mortem shows explains R1..R4 deltas)
//      * software-pipelined idx prefetch: next pixel's idx load issues
//        before the current gather's use -> 2 chains in flight per warp
//        at FULL grid width (unlike the R2/R4 grid-shrinking ILP attempts)
// ---------------------------------------------------------------------------

#define P_MAX 1200000

__device__ float4 g_shaded[P_MAX];   // shaded RGB per point (w-padded)

__device__ __forceinline__ float4 shade_one(
    float px, float py, float pz,
    float nx, float ny, float nz,
    float fr, float fg, float fb,
    float cx, float cy, float cz,
    float lx, float ly, float lz)
{
    float ndl     = nx * lx + ny * ly + nz * lz;
    float diffuse = fmaxf(ndl, 0.0f);

    float vx = cx - px, vy = cy - py, vz = cz - pz;
    {
        float n  = sqrtf(vx * vx + vy * vy + vz * vz);
        float vi = 1.0f / fmaxf(n, 1e-12f);
        vx *= vi; vy *= vi; vz *= vi;
    }
    float hx = lx + vx, hy = ly + vy, hz = lz + vz;
    {
        float n  = sqrtf(hx * hx + hy * hy + hz * hz);
        float hi = 1.0f / fmaxf(n, 1e-12f);
        hx *= hi; hy *= hi; hz *= hi;
    }
    float ndh = fmaxf(nx * hx + ny * hy + nz * hz, 0.0f);
    float x2  = ndh * ndh;
    float x4  = x2 * x2;
    float x8  = x4 * x4;
    float x16 = x8 * x8;
    float spec = x16 * x16;                 // ndh^32 exact (5 squarings)

    float scale = 0.3f + 0.7f * diffuse;
    float sterm = 0.2f * spec;

    float r = fminf(fmaxf(fr * scale + sterm, 0.0f), 1.0f);
    float g = fminf(fmaxf(fg * scale + sterm, 0.0f), 1.0f);
    float b = fminf(fmaxf(fb * scale + sterm, 0.0f), 1.0f);
    return make_float4(r, g, b, 0.0f);
}

__global__ void __launch_bounds__(256)
shade_kernel(const float* __restrict__ points,
             const float* __restrict__ features,
             const float* __restrict__ normals,
             const float* __restrict__ cam_centers,
             const float* __restrict__ light_dir,
             int P, int half, int pts_per_cloud)
{
    int t = blockIdx.x * blockDim.x + threadIdx.x;
    if (t >= half) return;

    int pA = t;
    int pB = t + half;
    bool hasB = (pB < P);

    float lx = __ldg(&light_dir[0]);
    float ly = __ldg(&light_dir[1]);
    float lz = __ldg(&light_dir[2]);
    {
        float n  = sqrtf(lx * lx + ly * ly + lz * lz);
        float li = 1.0f / fmaxf(n, 1e-12f);
        lx *= li; ly *= li; lz *= li;
    }

    float pxA = __ldcs(&points[3 * pA + 0]);
    float pyA = __ldcs(&points[3 * pA + 1]);
    float pzA = __ldcs(&points[3 * pA + 2]);
    float nxA = __ldcs(&normals[3 * pA + 0]);
    float nyA = __ldcs(&normals[3 * pA + 1]);
    float nzA = __ldcs(&normals[3 * pA + 2]);
    float frA = __ldcs(&features[3 * pA + 0]);
    float fgA = __ldcs(&features[3 * pA + 1]);
    float fbA = __ldcs(&features[3 * pA + 2]);

    int pBs = hasB ? pB : pA;
    float pxB = __ldcs(&points[3 * pBs + 0]);
    float pyB = __ldcs(&points[3 * pBs + 1]);
    float pzB = __ldcs(&points[3 * pBs + 2]);
    float nxB = __ldcs(&normals[3 * pBs + 0]);
    float nyB = __ldcs(&normals[3 * pBs + 1]);
    float nzB = __ldcs(&normals[3 * pBs + 2]);
    float frB = __ldcs(&features[3 * pBs + 0]);
    float fgB = __ldcs(&features[3 * pBs + 1]);
    float fbB = __ldcs(&features[3 * pBs + 2]);

    int cA = pA / pts_per_cloud;
    int cB = pBs / pts_per_cloud;
    float cxA = __ldg(&cam_centers[3 * cA + 0]);
    float cyA = __ldg(&cam_centers[3 * cA + 1]);
    float czA = __ldg(&cam_centers[3 * cA + 2]);
    float cxB = __ldg(&cam_centers[3 * cB + 0]);
    float cyB = __ldg(&cam_centers[3 * cB + 1]);
    float czB = __ldg(&cam_centers[3 * cB + 2]);

    g_shaded[pA] = shade_one(pxA, pyA, pzA, nxA, nyA, nzA, frA, fgA, fbA,
                             cxA, cyA, czA, lx, ly, lz);
    if (hasB) {
        g_shaded[pB] = shade_one(pxB, pyB, pzB, nxB, nyB, nzB, frB, fgB, fbB,
                                 cxB, cyB, czB, lx, ly, lz);
    }
}

__global__ void __launch_bounds__(256, 8)
composite_kernel(const int* __restrict__ idx,
                 float*     __restrict__ out,
                 int npix, int K)
{
    int tid    = blockIdx.x * blockDim.x + threadIdx.x;
    int stride = gridDim.x * blockDim.x;

    int i = tid;
    if (i >= npix) return;

    // software pipeline: prefetch idx for the next grid-stride iteration
    int nid = __ldcs(&idx[(long long)i * K]);

    while (true) {
        int id    = nid;
        int inext = i + stride;
        if (inext < npix)
            nid = __ldcs(&idx[(long long)inext * K]);   // overlaps gather below

        float4 v = (id >= 0) ? g_shaded[id]
                             : make_float4(1.0f, 1.0f, 1.0f, 0.0f);

        __stcs(&out[3 * i + 0], v.x);
        __stcs(&out[3 * i + 1], v.y);
        __stcs(&out[3 * i + 2], v.z);

        if (inext >= npix) break;
        i = inext;
    }
}

extern "C" void kernel_launch(void* const* d_in, const int* in_sizes, int n_in,
                              void* d_out, int out_size)
{
    const int*   idx         = (const int*)  d_in[0];
    const float* points      = (const float*)d_in[1];
    const float* features    = (const float*)d_in[2];
    const float* normals     = (const float*)d_in[3];
    const float* cam_centers = (const float*)d_in[4];
    const float* light_dir   = (const float*)d_in[6];
    float*       out         = (float*)d_out;

    int P = in_sizes[5];
    if (P > P_MAX) P = P_MAX;
    int B    = in_sizes[4] / 3;
    int ppc  = P / B;
    int npix = out_size / 3;
    int K    = in_sizes[0] / npix;

    {
        int half    = (P + 1) / 2;
        int threads = 256;
        int blocks  = (half + threads - 1) / threads;
        shade_kernel<<<blocks, threads>>>(points, features, normals,
                                          cam_centers, light_dir, P, half, ppc);
    }
    {
        // exactly one resident wave: SMs * 8 blocks of 256 (2048 thr/SM)
        int nsm = 148;
        cudaDeviceGetAttribute(&nsm, cudaDevAttrMultiProcessorCount, 0);
        int blocks  = nsm * 8;
        int threads = 256;
        int maxb    = (npix + threads - 1) / threads;
        if (blocks > maxb) blocks = maxb;
        composite_kernel<<<blocks, threads>>>(idx, out, npix, K);
    }
}